// round 14
// baseline (speedup 1.0000x reference)
#include <cuda_runtime.h>
#include <cuda_fp16.h>
#include <stdint.h>
#include <math.h>

#define B_ 4096
#define D_ 128
#define K_ 4096
#define E_ 1024
#define H_ 2048
#define V_ 64

// tensor scales (exact powers of 2; folded into epilogues)
#define SP_  64.0f      // score p scale
#define SE_  8192.0f    // e scale
#define SH_  8192.0f    // h scale
#define SP2_ 64.0f      // softmax p scale

typedef __half f16;

// ---------------- scratch (static device globals; no allocation) ----------------
__device__ float g_s[(size_t)B_ * K_];                       // diff, logits (fp32)
__device__ __align__(256) f16 g_p[(size_t)B_ * K_];          // p (score, then att)
__device__ __align__(256) f16 g_e[(size_t)B_ * E_];
__device__ __align__(256) f16 g_h[(size_t)B_ * H_];
__device__ __align__(256) f16 g_we[(size_t)E_ * K_];         // W_embed^T  [E,K] fp16
__device__ __align__(256) f16 g_wh[(size_t)H_ * E_];         // W_hidden^T [H,E]
__device__ __align__(256) f16 g_wa[(size_t)K_ * H_];         // W_att^T    [K,H]
__device__ __align__(256) f16 g_vt[(size_t)V_ * K_];         // values^T   [V,K]
__device__ __align__(256) f16 g_xc[(size_t)B_ * D_];         // x fp16
__device__ __align__(256) f16 g_kc[(size_t)K_ * D_];         // keys fp16
__device__ float g_part[(size_t)4 * B_ * V_];                // split-K partials
__device__ float g_x2[B_];
__device__ float g_k2[K_];
__device__ float g_rsc[B_];

// ---------------- helpers ----------------
__device__ __forceinline__ uint32_t smem_u32(const void* p) {
    uint32_t a;
    asm("{ .reg .u64 t; cvta.to.shared.u64 t, %1; cvt.u32.u64 %0, t; }" : "=r"(a) : "l"(p));
    return a;
}
__device__ __forceinline__ uint32_t pack2h(f16 a, f16 b) {
    __half2 t = __halves2half2(a, b);
    return *(uint32_t*)&t;
}

#define MMA_F16(d, a, b)                                                       \
    asm volatile(                                                              \
        "mma.sync.aligned.m16n8k16.row.col.f32.f16.f16.f32 "                   \
        "{%0,%1,%2,%3}, {%4,%5,%6,%7}, {%8,%9}, {%0,%1,%2,%3};\n"              \
        : "+f"(d[0]), "+f"(d[1]), "+f"(d[2]), "+f"(d[3])                       \
        : "r"(a[0]), "r"(a[1]), "r"(a[2]), "r"(a[3]), "r"(b[0]), "r"(b[1]))

#define LDSM4(r, addr)                                                         \
    asm volatile("ldmatrix.sync.aligned.m8n8.x4.shared.b16 {%0,%1,%2,%3}, [%4];" \
        : "=r"((r)[0]), "=r"((r)[1]), "=r"((r)[2]), "=r"((r)[3]) : "r"(addr))

// stage NBYTES of a f16 K-major tile (rows of 128B = 64 f16) into SW128-swizzled smem
template<int NBYTES, int NT>
__device__ __forceinline__ void stage_cp(uint32_t dst, const f16* src, int Kd) {
    const char* base = (const char*)src;
    int off = threadIdx.x * 16;
    #pragma unroll
    for (int it = 0; it < NBYTES / (NT * 16); ++it, off += NT * 16) {
        int row = off >> 7;
        int kb  = off & 127;
        const char* g = base + (size_t)row * ((size_t)Kd * 2) + kb;
        uint32_t d = dst + (uint32_t)(off ^ ((off >> 3) & 0x70));
        asm volatile("cp.async.cg.shared.global [%0], [%1], 16;" :: "r"(d), "l"(g));
    }
}

// ---------------- mma.sync GEMM: A, B single fp16, K-major ----------------
// D[m][n] = sum_k A[m][k]*B[n][k].  BK = 64 fixed.  WRM x WRN warps.
enum { EPI_NONE = 0, EPI_DIST = 1, EPI_RELU_BIAS = 2, EPI_BIAS = 3, EPI_SRELU_BIAS = 4 };

template<int BM, int BN, int WRM, int WRN>
__global__ void __launch_bounds__(WRM * WRN * 32)
tc_gemm(const f16* __restrict__ Ah, const f16* __restrict__ Bh,
        float* __restrict__ Cf, f16* __restrict__ Ch,
        int N, int Kd, int Kslice, int epi, float aScale, float outScale,
        const float* __restrict__ aux0, const float* __restrict__ aux1,
        const float* __restrict__ bias)
{
    constexpr int NT = WRM * WRN * 32;
    constexpr int WM = BM / WRM, WN = BN / WRN;
    constexpr int MF = WM / 16, NF = WN / 8, NB = NF / 2;
    constexpr int ABYTES = BM * 128, BBYTES = BN * 128;
    constexpr int STAGE = ABYTES + BBYTES;

    extern __shared__ char smem[];
    uint32_t sb = smem_u32(smem);
    const int tid = threadIdx.x, warp = tid >> 5, lane = tid & 31;
    const int gq = lane >> 2, tq = lane & 3;
    const int wm = (warp / WRN) * WM;
    const int wn = (warp % WRN) * WN;
    const int rowBase = blockIdx.y * BM;
    const int colBase = blockIdx.x * BN;
    const int kstart  = blockIdx.z * Kslice;
    const int KT = Kslice / 64;

    if (epi == EPI_NONE) Cf += (size_t)blockIdx.z * ((size_t)B_ * BN);

    const f16* Abh = Ah + (size_t)rowBase * Kd + kstart;
    const f16* Bbh = Bh + (size_t)colBase * Kd + kstart;

    // per-lane ldmatrix offsets: swizzled addr = row*128 + (kb ^ ((row&7)<<4))
    const int lr = lane & 15, lh = (lane >> 4) * 16;
    int aoff[MF], axr[MF], boff[NB], bxr[NB];
    #pragma unroll
    for (int fm = 0; fm < MF; ++fm) {
        int r = wm + fm * 16 + lr;
        aoff[fm] = r * 128; axr[fm] = (r & 7) << 4;
    }
    #pragma unroll
    for (int nb = 0; nb < NB; ++nb) {
        int r = wn + nb * 16 + lr;
        boff[nb] = r * 128; bxr[nb] = (r & 7) << 4;
    }

    float acc[MF][NF][4];
    #pragma unroll
    for (int i = 0; i < MF; ++i)
        #pragma unroll
        for (int j = 0; j < NF; ++j)
            #pragma unroll
            for (int c = 0; c < 4; ++c) acc[i][j][c] = 0.f;

    // ---- 2-stage cp.async pipeline ----
    #define STAGE_ALL(kt, buf) do {                                            \
        uint32_t d0 = sb + (buf) * STAGE;                                      \
        stage_cp<ABYTES, NT>(d0,          Abh + (kt) * 64, Kd);                \
        stage_cp<BBYTES, NT>(d0 + ABYTES, Bbh + (kt) * 64, Kd);                \
    } while (0)

    STAGE_ALL(0, 0);
    asm volatile("cp.async.commit_group;" ::: "memory");

    for (int kt = 0; kt < KT; ++kt) {
        if (kt + 1 < KT) {
            STAGE_ALL(kt + 1, (kt + 1) & 1);
            asm volatile("cp.async.commit_group;" ::: "memory");
            asm volatile("cp.async.wait_group 1;" ::: "memory");
        } else {
            asm volatile("cp.async.wait_group 0;" ::: "memory");
        }
        __syncthreads();

        const uint32_t base = sb + (kt & 1) * STAGE;
        const uint32_t Ahb = base;
        const uint32_t Bhb = base + ABYTES;

        #pragma unroll
        for (int ks = 0; ks < 4; ++ks) {
            const int kb = ks * 32 + lh;
            uint32_t ah[MF][4];
            #pragma unroll
            for (int fm = 0; fm < MF; ++fm)
                LDSM4(ah[fm], Ahb + aoff[fm] + (kb ^ axr[fm]));
            #pragma unroll
            for (int nb = 0; nb < NB; ++nb) {
                uint32_t b4[4];
                LDSM4(b4, Bhb + boff[nb] + (kb ^ bxr[nb]));
                #pragma unroll
                for (int odd = 0; odd < 2; ++odd) {
                    const int fn = nb * 2 + odd;
                    uint32_t bb[2] = { b4[odd], b4[odd + 2] };
                    #pragma unroll
                    for (int fm = 0; fm < MF; ++fm)
                        MMA_F16(acc[fm][fn], ah[fm], bb);
                }
            }
        }
        __syncthreads();
    }

    // ---- epilogue (runtime-selected; cold path) ----
    #pragma unroll
    for (int fm = 0; fm < MF; ++fm) {
        #pragma unroll
        for (int half = 0; half < 2; ++half) {
            const int row = rowBase + wm + fm * 16 + gq + half * 8;
            float r0 = 0.f;
            if (epi == EPI_DIST) r0 = aux0[row];
            if (epi == EPI_SRELU_BIAS) r0 = aux0[row] * aScale;
            #pragma unroll
            for (int fn = 0; fn < NF; ++fn) {
                const int col = colBase + wn + fn * 8 + tq * 2;
                float v0 = acc[fm][fn][half * 2 + 0];
                float v1 = acc[fm][fn][half * 2 + 1];
                if (epi == EPI_DIST) {
                    v0 = sqrtf(fmaxf(r0 + aux1[col]     - 2.f * v0, 0.f));
                    v1 = sqrtf(fmaxf(r0 + aux1[col + 1] - 2.f * v1, 0.f));
                } else if (epi == EPI_RELU_BIAS) {
                    v0 = fmaxf(fmaf(v0, aScale, bias[col]), 0.f);
                    v1 = fmaxf(fmaf(v1, aScale, bias[col + 1]), 0.f);
                } else if (epi == EPI_SRELU_BIAS) {
                    v0 = fmaxf(fmaf(v0, r0, bias[col]), 0.f);
                    v1 = fmaxf(fmaf(v1, r0, bias[col + 1]), 0.f);
                } else if (epi == EPI_BIAS) {
                    v0 = fmaf(v0, aScale, bias[col]);
                    v1 = fmaf(v1, aScale, bias[col + 1]);
                }
                if (epi == EPI_RELU_BIAS || epi == EPI_SRELU_BIAS) {
                    *(uint32_t*)&Ch[(size_t)row * N + col] =
                        pack2h(__float2half(v0 * outScale), __float2half(v1 * outScale));
                } else {
                    float2 o; o.x = v0; o.y = v1;
                    *(float2*)&Cf[(size_t)row * N + col] = o;
                }
            }
        }
    }
}

// ---------------- pre/post kernels ----------------
__global__ void sqnorm_kernel(const float* __restrict__ m, float* __restrict__ out, int rows) {
    int warp = (blockIdx.x * blockDim.x + threadIdx.x) >> 5;
    int lane = threadIdx.x & 31;
    if (warp >= rows) return;
    const float* r = m + (size_t)warp * D_;
    float s = 0.f;
    #pragma unroll
    for (int i = lane; i < D_; i += 32) { float v = r[i]; s += v * v; }
    #pragma unroll
    for (int o = 16; o; o >>= 1) s += __shfl_xor_sync(0xffffffffu, s, o);
    if (lane == 0) out[warp] = s;
}

// fp32 -> fp16 single, vectorized
__global__ void conv_kernel(const float* __restrict__ in, f16* __restrict__ o, int n4) {
    int i = blockIdx.x * blockDim.x + threadIdx.x;
    if (i >= n4) return;
    float4 v = ((const float4*)in)[i];
    ((uint2*)o)[i] = make_uint2(pack2h(__float2half(v.x), __float2half(v.y)),
                                pack2h(__float2half(v.z), __float2half(v.w)));
}

// in [R,C] fp32 row-major -> out [C,R] fp16 single
__global__ void transpose_h(const float* __restrict__ in, f16* __restrict__ o, int R, int C) {
    __shared__ float t[32][33];
    int cb = blockIdx.x * 32, rb = blockIdx.y * 32;
    int tx = threadIdx.x, ty = threadIdx.y;
    #pragma unroll
    for (int i = 0; i < 32; i += 8)
        t[ty + i][tx] = in[(size_t)(rb + ty + i) * C + cb + tx];
    __syncthreads();
    #pragma unroll
    for (int i = 0; i < 32; i += 8)
        o[(size_t)(cb + ty + i) * R + rb + tx] = __float2half(t[tx][ty + i]);
}

// score: p = exp(-10*diff/rowmax); store (p*SP_) f16 + rsc = 1/sum(p)
__global__ void __launch_bounds__(256) score_kernel(const float* __restrict__ s,
                                                    f16* __restrict__ ph,
                                                    float* __restrict__ rsc) {
    const int row = blockIdx.x;
    const float* p = s + (size_t)row * K_;
    const int tid = threadIdx.x;
    constexpr int PT = K_ / 256;
    float v[PT];
    float mx = 0.f;
    #pragma unroll
    for (int i = 0; i < PT; ++i) { v[i] = p[tid + i * 256]; mx = fmaxf(mx, v[i]); }
    __shared__ float red[256];
    red[tid] = mx; __syncthreads();
    #pragma unroll
    for (int o = 128; o; o >>= 1) { if (tid < o) red[tid] = fmaxf(red[tid], red[tid + o]); __syncthreads(); }
    mx = red[0];
    __syncthreads();
    const float scale = -10.f / mx;
    float sum = 0.f;
    #pragma unroll
    for (int i = 0; i < PT; ++i) { v[i] = __expf(v[i] * scale); sum += v[i]; }
    red[tid] = sum; __syncthreads();
    #pragma unroll
    for (int o = 128; o; o >>= 1) { if (tid < o) red[tid] += red[tid + o]; __syncthreads(); }
    #pragma unroll
    for (int i = 0; i < PT; ++i)
        ph[(size_t)row * K_ + tid + i * 256] = __float2half(v[i] * SP_);
    if (tid == 0) rsc[row] = 1.f / red[0];
}

// softmax: p = exp(l - rowmax); store (p*SP2_) f16 + rsc = 1/sum(p)
__global__ void __launch_bounds__(256) softmax_kernel(const float* __restrict__ s,
                                                      f16* __restrict__ ph,
                                                      float* __restrict__ rsc) {
    const int row = blockIdx.x;
    const float* p = s + (size_t)row * K_;
    const int tid = threadIdx.x;
    constexpr int PT = K_ / 256;
    float v[PT];
    float mx = -3.402823466e38f;
    #pragma unroll
    for (int i = 0; i < PT; ++i) { v[i] = p[tid + i * 256]; mx = fmaxf(mx, v[i]); }
    __shared__ float red[256];
    red[tid] = mx; __syncthreads();
    #pragma unroll
    for (int o = 128; o; o >>= 1) { if (tid < o) red[tid] = fmaxf(red[tid], red[tid + o]); __syncthreads(); }
    mx = red[0];
    __syncthreads();
    float sum = 0.f;
    #pragma unroll
    for (int i = 0; i < PT; ++i) { v[i] = __expf(v[i] - mx); sum += v[i]; }
    red[tid] = sum; __syncthreads();
    #pragma unroll
    for (int o = 128; o; o >>= 1) { if (tid < o) red[tid] += red[tid + o]; __syncthreads(); }
    #pragma unroll
    for (int i = 0; i < PT; ++i)
        ph[(size_t)row * K_ + tid + i * 256] = __float2half(v[i] * SP2_);
    if (tid == 0) rsc[row] = 1.f / red[0];
}

// out[b][v] = (rsc[b]/SP2_) * sum_j part[j][b][v]
__global__ void reduce_out(const float* __restrict__ part, const float* __restrict__ rsc,
                           float* __restrict__ out) {
    int i = blockIdx.x * blockDim.x + threadIdx.x;
    constexpr int BV = B_ * V_;
    if (i >= BV) return;
    float v = part[i] + part[i + BV] + part[i + 2 * BV] + part[i + 3 * BV];
    out[i] = v * rsc[i / V_] * (1.0f / SP2_);
}

// ---------------- launch ----------------
extern "C" void kernel_launch(void* const* d_in, const int* in_sizes, int n_in,
                              void* d_out, int out_size) {
    const float* x        = (const float*)d_in[0];
    const float* keys     = (const float*)d_in[1];
    const float* values   = (const float*)d_in[2];
    const float* W_embed  = (const float*)d_in[3];
    const float* b_embed  = (const float*)d_in[4];
    const float* W_hidden = (const float*)d_in[5];
    const float* b_hidden = (const float*)d_in[6];
    const float* W_att    = (const float*)d_in[7];
    const float* b_att    = (const float*)d_in[8];
    float* out = (float*)d_out;

    float *s, *x2, *k2, *rsc, *part;
    f16 *pc, *ec, *hc, *we, *wh, *wa, *vt, *xc, *kc;
    cudaGetSymbolAddress((void**)&s, g_s);
    cudaGetSymbolAddress((void**)&pc, g_p);
    cudaGetSymbolAddress((void**)&ec, g_e);
    cudaGetSymbolAddress((void**)&hc, g_h);
    cudaGetSymbolAddress((void**)&we, g_we);
    cudaGetSymbolAddress((void**)&wh, g_wh);
    cudaGetSymbolAddress((void**)&wa, g_wa);
    cudaGetSymbolAddress((void**)&vt, g_vt);
    cudaGetSymbolAddress((void**)&xc, g_xc);
    cudaGetSymbolAddress((void**)&kc, g_kc);
    cudaGetSymbolAddress((void**)&part, g_part);
    cudaGetSymbolAddress((void**)&x2, g_x2);
    cudaGetSymbolAddress((void**)&k2, g_k2);
    cudaGetSymbolAddress((void**)&rsc, g_rsc);

    // smem: 2 stages x (BM + BN)*128 bytes
    constexpr int SMEM_HUGE = 2 * ((256 + 256) * 128);  // 131072
    constexpr int SMEM_BIG  = 2 * ((256 + 128) * 128);  //  98304
    constexpr int SMEM_SML  = 2 * ((128 + 64) * 128);   //  49152
    cudaFuncSetAttribute((const void*)tc_gemm<256, 256, 4, 4>, cudaFuncAttributeMaxDynamicSharedMemorySize, SMEM_HUGE);
    cudaFuncSetAttribute((const void*)tc_gemm<256, 128, 4, 2>, cudaFuncAttributeMaxDynamicSharedMemorySize, SMEM_BIG);
    cudaFuncSetAttribute((const void*)tc_gemm<128, 64, 4, 2>,  cudaFuncAttributeMaxDynamicSharedMemorySize, SMEM_SML);

    // 0. preprocessing: norms, converts, weight transposes
    sqnorm_kernel<<<B_ / 8, 256>>>(x, x2, B_);
    sqnorm_kernel<<<K_ / 8, 256>>>(keys, k2, K_);
    conv_kernel<<<(B_ * D_ / 4 + 255) / 256, 256>>>(x, xc, B_ * D_ / 4);
    conv_kernel<<<(K_ * D_ / 4 + 255) / 256, 256>>>(keys, kc, K_ * D_ / 4);
    {
        dim3 blk(32, 8);
        transpose_h<<<dim3(E_ / 32, K_ / 32), blk>>>(W_embed, we, K_, E_);
        transpose_h<<<dim3(H_ / 32, E_ / 32), blk>>>(W_hidden, wh, E_, H_);
        transpose_h<<<dim3(K_ / 32, H_ / 32), blk>>>(W_att, wa, H_, K_);
        transpose_h<<<dim3(V_ / 32, K_ / 32), blk>>>(values, vt, K_, V_);
    }

    // 1. diff -> g_s (fp32)   [BN=256: 256 CTAs]
    tc_gemm<256, 256, 4, 4><<<dim3(K_ / 256, B_ / 256, 1), 512, SMEM_HUGE>>>(
        xc, kc, s, nullptr, K_, D_, D_, EPI_DIST, 1.f, 1.f, x2, k2, nullptr);

    // 2. score p (xSP_) + 1/sum
    score_kernel<<<B_, 256>>>(s, pc, rsc);

    // 3. e = relu(p @ We * rsc + b_embed); stored xSE_   [BN=128: 128 CTAs]
    tc_gemm<256, 128, 4, 2><<<dim3(E_ / 128, B_ / 256, 1), 256, SMEM_BIG>>>(
        pc, we, nullptr, ec, E_, K_, K_, EPI_SRELU_BIAS, 1.f / SP_, SE_, rsc, nullptr, b_embed);

    // 4. h = relu(e @ Wh + b_hidden); acc scaled by 1/SE_, stored xSH_   [BN=256: 128 CTAs]
    tc_gemm<256, 256, 4, 4><<<dim3(H_ / 256, B_ / 256, 1), 512, SMEM_HUGE>>>(
        ec, wh, nullptr, hc, H_, E_, E_, EPI_RELU_BIAS, 1.f / SE_, SH_, nullptr, nullptr, b_hidden);

    // 5. logits = h @ Wa / SH_ + b_att -> g_s (fp32)   [BN=256: 256 CTAs]
    tc_gemm<256, 256, 4, 4><<<dim3(K_ / 256, B_ / 256, 1), 512, SMEM_HUGE>>>(
        hc, wa, s, nullptr, K_, H_, H_, EPI_BIAS, 1.f / SH_, 1.f, nullptr, nullptr, b_att);

    // 6. softmax p (xSP2_) + 1/sum
    softmax_kernel<<<B_, 256>>>(s, pc, rsc);

    // 7. out partials (split-K x4), then reduce * rsc / SP2_
    tc_gemm<128, 64, 4, 2><<<dim3(1, B_ / 128, 4), 256, SMEM_SML>>>(
        pc, vt, part, nullptr, V_, K_, K_ / 4, EPI_NONE, 1.f, 1.f, nullptr, nullptr, nullptr);
    reduce_out<<<(B_ * V_ + 255) / 256, 256>>>(part, rsc, out);
}

// round 15
// speedup vs baseline: 9.0534x; 9.0534x over previous
#include <cuda_runtime.h>
#include <cuda_fp16.h>
#include <stdint.h>
#include <math.h>

#define B_ 4096
#define D_ 128
#define K_ 4096
#define E_ 1024
#define H_ 2048
#define V_ 64

// tensor scales (exact powers of 2; folded into epilogues)
#define SP_  64.0f      // score p scale
#define SE_  8192.0f    // e scale
#define SH_  8192.0f    // h scale
#define SP2_ 64.0f      // softmax p scale

typedef __half f16;

// ---------------- scratch (static device globals; no allocation) ----------------
__device__ float g_s[(size_t)B_ * K_];                       // diff, logits (fp32)
__device__ __align__(256) f16 g_p[(size_t)B_ * K_];          // p (score, then att)
__device__ __align__(256) f16 g_e[(size_t)B_ * E_];
__device__ __align__(256) f16 g_h[(size_t)B_ * H_];
__device__ __align__(256) f16 g_we[(size_t)E_ * K_];         // W_embed^T  [E,K] fp16
__device__ __align__(256) f16 g_wh[(size_t)H_ * E_];         // W_hidden^T [H,E]
__device__ __align__(256) f16 g_wa[(size_t)K_ * H_];         // W_att^T    [K,H]
__device__ __align__(256) f16 g_vt[(size_t)V_ * K_];         // values^T   [V,K]
__device__ __align__(256) f16 g_xc[(size_t)B_ * D_];         // x fp16
__device__ __align__(256) f16 g_kc[(size_t)K_ * D_];         // keys fp16
__device__ float g_part[(size_t)4 * B_ * V_];                // split-K partials
__device__ float g_x2[B_];
__device__ float g_k2[K_];
__device__ float g_rsc[B_];

// ---------------- helpers ----------------
__device__ __forceinline__ uint32_t smem_u32(const void* p) {
    uint32_t a;
    asm("{ .reg .u64 t; cvta.to.shared.u64 t, %1; cvt.u32.u64 %0, t; }" : "=r"(a) : "l"(p));
    return a;
}
__device__ __forceinline__ uint32_t pack2h(f16 a, f16 b) {
    __half2 t = __halves2half2(a, b);
    return *(uint32_t*)&t;
}

#define MMA_F16(d, a, b)                                                       \
    asm volatile(                                                              \
        "mma.sync.aligned.m16n8k16.row.col.f32.f16.f16.f32 "                   \
        "{%0,%1,%2,%3}, {%4,%5,%6,%7}, {%8,%9}, {%0,%1,%2,%3};\n"              \
        : "+f"(d[0]), "+f"(d[1]), "+f"(d[2]), "+f"(d[3])                       \
        : "r"(a[0]), "r"(a[1]), "r"(a[2]), "r"(a[3]), "r"(b[0]), "r"(b[1]))

#define LDSM4(r, addr)                                                         \
    asm volatile("ldmatrix.sync.aligned.m8n8.x4.shared.b16 {%0,%1,%2,%3}, [%4];" \
        : "=r"((r)[0]), "=r"((r)[1]), "=r"((r)[2]), "=r"((r)[3]) : "r"(addr))

// stage NBYTES of a f16 K-major tile (rows of 128B = 64 f16) into SW128-swizzled smem
template<int NBYTES, int NT>
__device__ __forceinline__ void stage_cp(uint32_t dst, const f16* src, int Kd) {
    const char* base = (const char*)src;
    int off = threadIdx.x * 16;
    #pragma unroll
    for (int it = 0; it < NBYTES / (NT * 16); ++it, off += NT * 16) {
        int row = off >> 7;
        int kb  = off & 127;
        const char* g = base + (size_t)row * ((size_t)Kd * 2) + kb;
        uint32_t d = dst + (uint32_t)(off ^ ((off >> 3) & 0x70));
        asm volatile("cp.async.cg.shared.global [%0], [%1], 16;" :: "r"(d), "l"(g));
    }
}

// ---------------- mma.sync GEMM: A, B single fp16, K-major ----------------
// D[m][n] = sum_k A[m][k]*B[n][k].  BK = 64 fixed.  WRM x WRN warps.
enum { EPI_NONE = 0, EPI_DIST = 1, EPI_RELU_BIAS = 2, EPI_BIAS = 3, EPI_SRELU_BIAS = 4 };

template<int BM, int BN, int WRM, int WRN, int MINB>
__global__ void __launch_bounds__(WRM * WRN * 32, MINB)
tc_gemm(const f16* __restrict__ Ah, const f16* __restrict__ Bh,
        float* __restrict__ Cf, f16* __restrict__ Ch,
        int N, int Kd, int Kslice, int epi, float aScale, float outScale,
        const float* __restrict__ aux0, const float* __restrict__ aux1,
        const float* __restrict__ bias)
{
    constexpr int NT = WRM * WRN * 32;
    constexpr int WM = BM / WRM, WN = BN / WRN;
    constexpr int MF = WM / 16, NF = WN / 8, NB = NF / 2;
    constexpr int ABYTES = BM * 128, BBYTES = BN * 128;
    constexpr int STAGE = ABYTES + BBYTES;

    extern __shared__ char smem[];
    uint32_t sb = smem_u32(smem);
    const int tid = threadIdx.x, warp = tid >> 5, lane = tid & 31;
    const int gq = lane >> 2, tq = lane & 3;
    const int wm = (warp / WRN) * WM;
    const int wn = (warp % WRN) * WN;
    const int rowBase = blockIdx.y * BM;
    const int colBase = blockIdx.x * BN;
    const int kstart  = blockIdx.z * Kslice;
    const int KT = Kslice / 64;

    if (epi == EPI_NONE) Cf += (size_t)blockIdx.z * ((size_t)B_ * BN);

    const f16* Abh = Ah + (size_t)rowBase * Kd + kstart;
    const f16* Bbh = Bh + (size_t)colBase * Kd + kstart;

    // per-lane ldmatrix offsets: swizzled addr = row*128 + (kb ^ ((row&7)<<4))
    const int lr = lane & 15, lh = (lane >> 4) * 16;
    int aoff[MF], axr[MF], boff[NB], bxr[NB];
    #pragma unroll
    for (int fm = 0; fm < MF; ++fm) {
        int r = wm + fm * 16 + lr;
        aoff[fm] = r * 128; axr[fm] = (r & 7) << 4;
    }
    #pragma unroll
    for (int nb = 0; nb < NB; ++nb) {
        int r = wn + nb * 16 + lr;
        boff[nb] = r * 128; bxr[nb] = (r & 7) << 4;
    }

    float acc[MF][NF][4];
    #pragma unroll
    for (int i = 0; i < MF; ++i)
        #pragma unroll
        for (int j = 0; j < NF; ++j)
            #pragma unroll
            for (int c = 0; c < 4; ++c) acc[i][j][c] = 0.f;

    // ---- 2-stage cp.async pipeline ----
    #define STAGE_ALL(kt, buf) do {                                            \
        uint32_t d0 = sb + (buf) * STAGE;                                      \
        stage_cp<ABYTES, NT>(d0,          Abh + (kt) * 64, Kd);                \
        stage_cp<BBYTES, NT>(d0 + ABYTES, Bbh + (kt) * 64, Kd);                \
    } while (0)

    STAGE_ALL(0, 0);
    asm volatile("cp.async.commit_group;" ::: "memory");

    for (int kt = 0; kt < KT; ++kt) {
        if (kt + 1 < KT) {
            STAGE_ALL(kt + 1, (kt + 1) & 1);
            asm volatile("cp.async.commit_group;" ::: "memory");
            asm volatile("cp.async.wait_group 1;" ::: "memory");
        } else {
            asm volatile("cp.async.wait_group 0;" ::: "memory");
        }
        __syncthreads();

        const uint32_t base = sb + (kt & 1) * STAGE;
        const uint32_t Ahb = base;
        const uint32_t Bhb = base + ABYTES;

        #pragma unroll
        for (int ks = 0; ks < 4; ++ks) {
            const int kb = ks * 32 + lh;
            uint32_t ah[MF][4];
            #pragma unroll
            for (int fm = 0; fm < MF; ++fm)
                LDSM4(ah[fm], Ahb + aoff[fm] + (kb ^ axr[fm]));
            #pragma unroll
            for (int nb = 0; nb < NB; ++nb) {
                uint32_t b4[4];
                LDSM4(b4, Bhb + boff[nb] + (kb ^ bxr[nb]));
                #pragma unroll
                for (int odd = 0; odd < 2; ++odd) {
                    const int fn = nb * 2 + odd;
                    uint32_t bb[2] = { b4[odd], b4[odd + 2] };
                    #pragma unroll
                    for (int fm = 0; fm < MF; ++fm)
                        MMA_F16(acc[fm][fn], ah[fm], bb);
                }
            }
        }
        __syncthreads();
    }

    // ---- epilogue (runtime-selected; cold path) ----
    #pragma unroll
    for (int fm = 0; fm < MF; ++fm) {
        #pragma unroll
        for (int half = 0; half < 2; ++half) {
            const int row = rowBase + wm + fm * 16 + gq + half * 8;
            float r0 = 0.f;
            if (epi == EPI_DIST) r0 = aux0[row];
            if (epi == EPI_SRELU_BIAS) r0 = aux0[row] * aScale;
            #pragma unroll
            for (int fn = 0; fn < NF; ++fn) {
                const int col = colBase + wn + fn * 8 + tq * 2;
                float v0 = acc[fm][fn][half * 2 + 0];
                float v1 = acc[fm][fn][half * 2 + 1];
                if (epi == EPI_DIST) {
                    v0 = sqrtf(fmaxf(r0 + aux1[col]     - 2.f * v0, 0.f));
                    v1 = sqrtf(fmaxf(r0 + aux1[col + 1] - 2.f * v1, 0.f));
                } else if (epi == EPI_RELU_BIAS) {
                    v0 = fmaxf(fmaf(v0, aScale, bias[col]), 0.f);
                    v1 = fmaxf(fmaf(v1, aScale, bias[col + 1]), 0.f);
                } else if (epi == EPI_SRELU_BIAS) {
                    v0 = fmaxf(fmaf(v0, r0, bias[col]), 0.f);
                    v1 = fmaxf(fmaf(v1, r0, bias[col + 1]), 0.f);
                } else if (epi == EPI_BIAS) {
                    v0 = fmaf(v0, aScale, bias[col]);
                    v1 = fmaf(v1, aScale, bias[col + 1]);
                }
                if (epi == EPI_RELU_BIAS || epi == EPI_SRELU_BIAS) {
                    *(uint32_t*)&Ch[(size_t)row * N + col] =
                        pack2h(__float2half(v0 * outScale), __float2half(v1 * outScale));
                } else {
                    float2 o; o.x = v0; o.y = v1;
                    *(float2*)&Cf[(size_t)row * N + col] = o;
                }
            }
        }
    }
}

// ---------------- pre/post kernels ----------------
// fused: squared row norm + fp32->fp16 convert (one warp per row, D=128)
__global__ void sqnorm_conv_kernel(const float* __restrict__ m, float* __restrict__ nrm,
                                   f16* __restrict__ oc, int rows) {
    int warp = (blockIdx.x * blockDim.x + threadIdx.x) >> 5;
    int lane = threadIdx.x & 31;
    if (warp >= rows) return;
    const float* r = m + (size_t)warp * D_;
    float4 v = ((const float4*)r)[lane];
    float s = v.x * v.x + v.y * v.y + v.z * v.z + v.w * v.w;
    ((uint2*)(oc + (size_t)warp * D_))[lane] =
        make_uint2(pack2h(__float2half(v.x), __float2half(v.y)),
                   pack2h(__float2half(v.z), __float2half(v.w)));
    #pragma unroll
    for (int o = 16; o; o >>= 1) s += __shfl_xor_sync(0xffffffffu, s, o);
    if (lane == 0) nrm[warp] = s;
}

// in [R,C] fp32 row-major -> out [C,R] fp16 single
__global__ void transpose_h(const float* __restrict__ in, f16* __restrict__ o, int R, int C) {
    __shared__ float t[32][33];
    int cb = blockIdx.x * 32, rb = blockIdx.y * 32;
    int tx = threadIdx.x, ty = threadIdx.y;
    #pragma unroll
    for (int i = 0; i < 32; i += 8)
        t[ty + i][tx] = in[(size_t)(rb + ty + i) * C + cb + tx];
    __syncthreads();
    #pragma unroll
    for (int i = 0; i < 32; i += 8)
        o[(size_t)(cb + ty + i) * R + rb + tx] = __float2half(t[tx][ty + i]);
}

// score: p = exp(-10*diff/rowmax); store (p*SP_) f16 + rsc = 1/sum(p)
__global__ void __launch_bounds__(256) score_kernel(const float* __restrict__ s,
                                                    f16* __restrict__ ph,
                                                    float* __restrict__ rsc) {
    const int row = blockIdx.x;
    const float* p = s + (size_t)row * K_;
    const int tid = threadIdx.x;
    constexpr int PT = K_ / 256;
    float v[PT];
    float mx = 0.f;
    #pragma unroll
    for (int i = 0; i < PT; ++i) { v[i] = p[tid + i * 256]; mx = fmaxf(mx, v[i]); }
    __shared__ float red[256];
    red[tid] = mx; __syncthreads();
    #pragma unroll
    for (int o = 128; o; o >>= 1) { if (tid < o) red[tid] = fmaxf(red[tid], red[tid + o]); __syncthreads(); }
    mx = red[0];
    __syncthreads();
    const float scale = -10.f / mx;
    float sum = 0.f;
    #pragma unroll
    for (int i = 0; i < PT; ++i) { v[i] = __expf(v[i] * scale); sum += v[i]; }
    red[tid] = sum; __syncthreads();
    #pragma unroll
    for (int o = 128; o; o >>= 1) { if (tid < o) red[tid] += red[tid + o]; __syncthreads(); }
    #pragma unroll
    for (int i = 0; i < PT; ++i)
        ph[(size_t)row * K_ + tid + i * 256] = __float2half(v[i] * SP_);
    if (tid == 0) rsc[row] = 1.f / red[0];
}

// softmax: p = exp(l - rowmax); store (p*SP2_) f16 + rsc = 1/sum(p)
__global__ void __launch_bounds__(256) softmax_kernel(const float* __restrict__ s,
                                                      f16* __restrict__ ph,
                                                      float* __restrict__ rsc) {
    const int row = blockIdx.x;
    const float* p = s + (size_t)row * K_;
    const int tid = threadIdx.x;
    constexpr int PT = K_ / 256;
    float v[PT];
    float mx = -3.402823466e38f;
    #pragma unroll
    for (int i = 0; i < PT; ++i) { v[i] = p[tid + i * 256]; mx = fmaxf(mx, v[i]); }
    __shared__ float red[256];
    red[tid] = mx; __syncthreads();
    #pragma unroll
    for (int o = 128; o; o >>= 1) { if (tid < o) red[tid] = fmaxf(red[tid], red[tid + o]); __syncthreads(); }
    mx = red[0];
    __syncthreads();
    float sum = 0.f;
    #pragma unroll
    for (int i = 0; i < PT; ++i) { v[i] = __expf(v[i] - mx); sum += v[i]; }
    red[tid] = sum; __syncthreads();
    #pragma unroll
    for (int o = 128; o; o >>= 1) { if (tid < o) red[tid] += red[tid + o]; __syncthreads(); }
    #pragma unroll
    for (int i = 0; i < PT; ++i)
        ph[(size_t)row * K_ + tid + i * 256] = __float2half(v[i] * SP2_);
    if (tid == 0) rsc[row] = 1.f / red[0];
}

// out[b][v] = (rsc[b]/SP2_) * sum_j part[j][b][v]
__global__ void reduce_out(const float* __restrict__ part, const float* __restrict__ rsc,
                           float* __restrict__ out) {
    int i = blockIdx.x * blockDim.x + threadIdx.x;
    constexpr int BV = B_ * V_;
    if (i >= BV) return;
    float v = part[i] + part[i + BV] + part[i + 2 * BV] + part[i + 3 * BV];
    out[i] = v * rsc[i / V_] * (1.0f / SP2_);
}

// ---------------- launch ----------------
extern "C" void kernel_launch(void* const* d_in, const int* in_sizes, int n_in,
                              void* d_out, int out_size) {
    const float* x        = (const float*)d_in[0];
    const float* keys     = (const float*)d_in[1];
    const float* values   = (const float*)d_in[2];
    const float* W_embed  = (const float*)d_in[3];
    const float* b_embed  = (const float*)d_in[4];
    const float* W_hidden = (const float*)d_in[5];
    const float* b_hidden = (const float*)d_in[6];
    const float* W_att    = (const float*)d_in[7];
    const float* b_att    = (const float*)d_in[8];
    float* out = (float*)d_out;

    float *s, *x2, *k2, *rsc, *part;
    f16 *pc, *ec, *hc, *we, *wh, *wa, *vt, *xc, *kc;
    cudaGetSymbolAddress((void**)&s, g_s);
    cudaGetSymbolAddress((void**)&pc, g_p);
    cudaGetSymbolAddress((void**)&ec, g_e);
    cudaGetSymbolAddress((void**)&hc, g_h);
    cudaGetSymbolAddress((void**)&we, g_we);
    cudaGetSymbolAddress((void**)&wh, g_wh);
    cudaGetSymbolAddress((void**)&wa, g_wa);
    cudaGetSymbolAddress((void**)&vt, g_vt);
    cudaGetSymbolAddress((void**)&xc, g_xc);
    cudaGetSymbolAddress((void**)&kc, g_kc);
    cudaGetSymbolAddress((void**)&part, g_part);
    cudaGetSymbolAddress((void**)&x2, g_x2);
    cudaGetSymbolAddress((void**)&k2, g_k2);
    cudaGetSymbolAddress((void**)&rsc, g_rsc);

    // smem: 2 stages x (BM + BN)*128 bytes
    constexpr int SMEM_MID = 2 * ((128 + 128) * 128);   // 65536  (2 CTAs/SM)
    constexpr int SMEM_SML = 2 * ((128 + 64) * 128);    // 49152
    cudaFuncSetAttribute((const void*)tc_gemm<128, 128, 2, 4, 2>, cudaFuncAttributeMaxDynamicSharedMemorySize, SMEM_MID);
    cudaFuncSetAttribute((const void*)tc_gemm<128, 64, 4, 2, 1>,  cudaFuncAttributeMaxDynamicSharedMemorySize, SMEM_SML);

    // 0. preprocessing: fused norm+convert, weight transposes
    sqnorm_conv_kernel<<<B_ / 8, 256>>>(x, x2, xc, B_);
    sqnorm_conv_kernel<<<K_ / 8, 256>>>(keys, k2, kc, K_);
    {
        dim3 blk(32, 8);
        transpose_h<<<dim3(E_ / 32, K_ / 32), blk>>>(W_embed, we, K_, E_);
        transpose_h<<<dim3(H_ / 32, E_ / 32), blk>>>(W_hidden, wh, E_, H_);
        transpose_h<<<dim3(K_ / 32, H_ / 32), blk>>>(W_att, wa, H_, K_);
        transpose_h<<<dim3(V_ / 32, K_ / 32), blk>>>(values, vt, K_, V_);
    }

    // 1. diff -> g_s (fp32)   [grid 32x32 = 1024 CTAs, 2/SM]
    tc_gemm<128, 128, 2, 4, 2><<<dim3(K_ / 128, B_ / 128, 1), 256, SMEM_MID>>>(
        xc, kc, s, nullptr, K_, D_, D_, EPI_DIST, 1.f, 1.f, x2, k2, nullptr);

    // 2. score p (xSP_) + 1/sum
    score_kernel<<<B_, 256>>>(s, pc, rsc);

    // 3. e = relu(p @ We * rsc + b_embed); stored xSE_   [grid 8x32 = 256]
    tc_gemm<128, 128, 2, 4, 2><<<dim3(E_ / 128, B_ / 128, 1), 256, SMEM_MID>>>(
        pc, we, nullptr, ec, E_, K_, K_, EPI_SRELU_BIAS, 1.f / SP_, SE_, rsc, nullptr, b_embed);

    // 4. h = relu(e @ Wh + b_hidden); acc scaled by 1/SE_, stored xSH_   [grid 16x32 = 512]
    tc_gemm<128, 128, 2, 4, 2><<<dim3(H_ / 128, B_ / 128, 1), 256, SMEM_MID>>>(
        ec, wh, nullptr, hc, H_, E_, E_, EPI_RELU_BIAS, 1.f / SE_, SH_, nullptr, nullptr, b_hidden);

    // 5. logits = h @ Wa / SH_ + b_att -> g_s (fp32)   [grid 32x32 = 1024]
    tc_gemm<128, 128, 2, 4, 2><<<dim3(K_ / 128, B_ / 128, 1), 256, SMEM_MID>>>(
        hc, wa, s, nullptr, K_, H_, H_, EPI_BIAS, 1.f / SH_, 1.f, nullptr, nullptr, b_att);

    // 6. softmax p (xSP2_) + 1/sum
    softmax_kernel<<<B_, 256>>>(s, pc, rsc);

    // 7. out partials (split-K x4), then reduce * rsc / SP2_
    tc_gemm<128, 64, 4, 2, 1><<<dim3(1, B_ / 128, 4), 256, SMEM_SML>>>(
        pc, vt, part, nullptr, V_, K_, K_ / 4, EPI_NONE, 1.f, 1.f, nullptr, nullptr, nullptr);
    reduce_out<<<(B_ * V_ + 255) / 256, 256>>>(part, rsc, out);
}